// round 8
// baseline (speedup 1.0000x reference)
#include <cuda_runtime.h>
#include <cstdint>

#define N_ 4096
#define D_ 5000
#define H_ 512
#define C_ 4
#define L_ 8
#define BK 16
#define ST 68
#define SP 20
#define CHUNK (1024 * 512)

// ---------------- scratch: 56 MiB ----------------
__device__ float g_xhat[N_ * H_];
__device__ float g_xr[N_ * H_];
__device__ float g_xz[N_ * H_];
__device__ float g_xh[N_ * H_];
__device__ float g_h[N_ * H_];      // hidden state (+ per-level z stash)
__device__ float g_hs[N_ * H_];     // chunk0: hs
__device__ float g_rhs[N_ * H_];    // split-K partials, then hs*r
__device__ int   g_rows[N_];
__device__ int   g_off[16];
__device__ int   g_fill[L_];

// ---------------- level bucketing ----------------
__global__ void lvl_init_k() {
    int t = threadIdx.x;
    if (t < 16) g_off[t] = 0;
    if (t < L_) g_fill[t] = 0;
}
__global__ void lvl_hist_k(const int* __restrict__ level) {
    int i = blockIdx.x * blockDim.x + threadIdx.x;
    if (i < N_) atomicAdd(&g_off[level[i] + 1], 1);
}
__global__ void lvl_scan_k() {
    if (threadIdx.x == 0)
        for (int j = 1; j <= L_; j++) g_off[j] += g_off[j - 1];
}
__global__ void lvl_scatter_k(const int* __restrict__ level) {
    int i = blockIdx.x * blockDim.x + threadIdx.x;
    if (i < N_) {
        int l = level[i];
        int p = atomicAdd(&g_fill[l], 1);
        g_rows[g_off[l] + p] = i;
    }
}
__global__ void zero_h_k() {
    int i = blockIdx.x * blockDim.x + threadIdx.x;
    int stride = gridDim.x * blockDim.x;
    for (; i < N_ * H_; i += stride) g_h[i] = 0.f;
}
// zero g_hs rows 0..M-1 (used at the deepest level where h == 0)
__global__ void zero_hs_k(int lvl) {
    int M = g_off[lvl + 1] - g_off[lvl];
    long idx = (long)blockIdx.x * 256 + threadIdx.x;
    int m = (int)(idx >> 9);
    if (m < M) g_hs[idx] = 0.f;
}

__device__ __forceinline__ float sigm_(float v) { return 1.f / (1.f + expf(-v)); }

// ================= 3xTF32 mma machinery (validated) =================
__device__ __forceinline__ uint32_t fu(float f) { return __float_as_uint(f); }
__device__ __forceinline__ void tf32split(float v, float& hi, float& lo) {
    uint32_t b;
    asm("cvt.rna.tf32.f32 %0, %1;" : "=r"(b) : "f"(v));
    hi = __uint_as_float(b);
    lo = v - hi;
}
__device__ __forceinline__ void mma8(float c[4], const uint32_t a[4],
                                     uint32_t b0, uint32_t b1) {
    asm volatile(
        "mma.sync.aligned.m16n8k8.row.col.f32.tf32.tf32.f32 "
        "{%0,%1,%2,%3}, {%4,%5,%6,%7}, {%8,%9}, {%0,%1,%2,%3};"
        : "+f"(c[0]), "+f"(c[1]), "+f"(c[2]), "+f"(c[3])
        : "r"(a[0]), "r"(a[1]), "r"(a[2]), "r"(a[3]), "r"(b0), "r"(b1));
}

// raw float4 load of a 64x16 tile element (256 threads, one float4 each)
__device__ __forceinline__ float4 ldraw(const float* __restrict__ src, long ld,
                                        int K, int k0, int r0) {
    int lr = threadIdx.x >> 2;
    int lc = (threadIdx.x & 3) << 2;
    int gk = k0 + lc;
    float4 v = make_float4(0.f, 0.f, 0.f, 0.f);
    if (gk < K) v = *(const float4*)(src + (long)(r0 + lr) * ld + gk);
    return v;
}
// gathered-row variant (A = adj[rows[...]])
__device__ __forceinline__ float4 ldrawG(const float* __restrict__ src, long ld,
                                         int k0, int r0, int M,
                                         const int* __restrict__ rows) {
    int lr = threadIdx.x >> 2;
    int lc = (threadIdx.x & 3) << 2;
    int gm = r0 + lr;
    float4 v = make_float4(0.f, 0.f, 0.f, 0.f);
    if (gm < M) v = *(const float4*)(src + (long)rows[gm] * ld + k0 + lc);
    return v;
}
__device__ __forceinline__ void split_store(float (*sH)[SP], float (*sL)[SP], float4 v) {
    int lr = threadIdx.x >> 2;
    int lc = (threadIdx.x & 3) << 2;
    float h0, l0, h1, l1, h2, l2, h3, l3;
    tf32split(v.x, h0, l0); tf32split(v.y, h1, l1);
    tf32split(v.z, h2, l2); tf32split(v.w, h3, l3);
    *(float4*)&sH[lr][lc] = make_float4(h0, h1, h2, h3);
    *(float4*)&sL[lr][lc] = make_float4(l0, l1, l2, l3);
}
// B tile from NN layout g_h[k0..k0+15][n0..n0+63], staged transposed to [n][k]
__device__ __forceinline__ float4 ldrawNN(const float* __restrict__ src, int k0, int n0) {
    int kk = threadIdx.x >> 4;          // 0..15
    int c  = (threadIdx.x & 15) << 2;   // 0..60
    return *(const float4*)(src + (long)(k0 + kk) * H_ + n0 + c);
}
__device__ __forceinline__ void split_storeNN(float (*sH)[SP], float (*sL)[SP], float4 v) {
    int kk = threadIdx.x >> 4;
    int c  = (threadIdx.x & 15) << 2;
    float h, l;
    tf32split(v.x, h, l); sH[c + 0][kk] = h; sL[c + 0][kk] = l;
    tf32split(v.y, h, l); sH[c + 1][kk] = h; sL[c + 1][kk] = l;
    tf32split(v.z, h, l); sH[c + 2][kk] = h; sL[c + 2][kk] = l;
    tf32split(v.w, h, l); sH[c + 3][kk] = h; sL[c + 3][kk] = l;
}
__device__ __forceinline__ void mma_tile(float acc[2][2][4],
                                         const float (*sAh)[SP], const float (*sAl)[SP],
                                         const float (*sBh)[SP], const float (*sBl)[SP],
                                         int wm, int wn, int g, int tg) {
#pragma unroll
    for (int kk = 0; kk < 16; kk += 8) {
        uint32_t ah[2][4], al[2][4];
#pragma unroll
        for (int mt = 0; mt < 2; mt++) {
            int r0 = wm + mt * 16 + g;
            ah[mt][0] = fu(sAh[r0][kk + tg]);     ah[mt][1] = fu(sAh[r0 + 8][kk + tg]);
            ah[mt][2] = fu(sAh[r0][kk + tg + 4]); ah[mt][3] = fu(sAh[r0 + 8][kk + tg + 4]);
            al[mt][0] = fu(sAl[r0][kk + tg]);     al[mt][1] = fu(sAl[r0 + 8][kk + tg]);
            al[mt][2] = fu(sAl[r0][kk + tg + 4]); al[mt][3] = fu(sAl[r0 + 8][kk + tg + 4]);
        }
#pragma unroll
        for (int nt = 0; nt < 2; nt++) {
            int c = wn + nt * 8 + g;
            uint32_t bh0 = fu(sBh[c][kk + tg]), bh1 = fu(sBh[c][kk + tg + 4]);
            uint32_t bl0 = fu(sBl[c][kk + tg]), bl1 = fu(sBl[c][kk + tg + 4]);
#pragma unroll
            for (int mt = 0; mt < 2; mt++) {
                mma8(acc[mt][nt], ah[mt], bh0, bh1);
                mma8(acc[mt][nt], al[mt], bh0, bh1);
                mma8(acc[mt][nt], ah[mt], bl0, bl1);
            }
        }
    }
}

// ---------------- x_hat = x @ E_w^T  (3xTF32, double-buffered) ----------------
__global__ __launch_bounds__(256) void mm_xhat(const float* __restrict__ x,
                                               const float* __restrict__ Ew) {
    __shared__ float sAh[2][64][SP], sAl[2][64][SP], sBh[2][64][SP], sBl[2][64][SP];
    int m0 = blockIdx.y * 64, n0 = blockIdx.x * 64;
    int wid = threadIdx.x >> 5, lane = threadIdx.x & 31;
    int g = lane >> 2, tg = lane & 3;
    int wm = (wid & 1) * 32, wn = (wid >> 1) * 16;
    float acc[2][2][4] = {};
    const int nsl = (D_ + BK - 1) / BK;   // 313
    float4 ra = ldraw(x, D_, D_, 0, m0);
    float4 rb = ldraw(Ew, D_, D_, 0, n0);
    split_store(sAh[0], sAl[0], ra);
    split_store(sBh[0], sBl[0], rb);
    __syncthreads();
    int cur = 0;
    for (int s = 0; s < nsl; s++) {
        if (s + 1 < nsl) {
            ra = ldraw(x, D_, D_, (s + 1) * BK, m0);
            rb = ldraw(Ew, D_, D_, (s + 1) * BK, n0);
        }
        mma_tile(acc, sAh[cur], sAl[cur], sBh[cur], sBl[cur], wm, wn, g, tg);
        if (s + 1 < nsl) {
            split_store(sAh[1 - cur], sAl[1 - cur], ra);
            split_store(sBh[1 - cur], sBl[1 - cur], rb);
        }
        __syncthreads();
        cur ^= 1;
    }
#pragma unroll
    for (int mt = 0; mt < 2; mt++)
#pragma unroll
        for (int nt = 0; nt < 2; nt++) {
            int r = m0 + wm + mt * 16 + g;
            int c = n0 + wn + nt * 8 + 2 * tg;
            g_xhat[(long)r * H_ + c]           = acc[mt][nt][0];
            g_xhat[(long)r * H_ + c + 1]       = acc[mt][nt][1];
            g_xhat[(long)(r + 8) * H_ + c]     = acc[mt][nt][2];
            g_xhat[(long)(r + 8) * H_ + c + 1] = acc[mt][nt][3];
        }
}

// ---------------- xr/xz/xh = xhat @ {Wr,Wz,Wh}^T  (3xTF32, shared A) ---------
__global__ __launch_bounds__(256) void mm_xw(const float* __restrict__ Wr,
                                             const float* __restrict__ Wz,
                                             const float* __restrict__ Wh) {
    __shared__ float sAh[64][SP], sAl[64][SP];
    __shared__ float sBh[3][64][SP], sBl[3][64][SP];
    int m0 = blockIdx.y * 64, n0 = blockIdx.x * 64;
    int wid = threadIdx.x >> 5, lane = threadIdx.x & 31;
    int g = lane >> 2, tg = lane & 3;
    int wm = (wid & 1) * 32, wn = (wid >> 1) * 16;
    float acc[3][2][2][4] = {};
    for (int k0 = 0; k0 < H_; k0 += BK) {
        split_store(sAh, sAl, ldraw(g_xhat, H_, H_, k0, m0));
        split_store(sBh[0], sBl[0], ldraw(Wr, H_, H_, k0, n0));
        split_store(sBh[1], sBl[1], ldraw(Wz, H_, H_, k0, n0));
        split_store(sBh[2], sBl[2], ldraw(Wh, H_, H_, k0, n0));
        __syncthreads();
#pragma unroll
        for (int w = 0; w < 3; w++)
            mma_tile(acc[w], sAh, sAl, sBh[w], sBl[w], wm, wn, g, tg);
        __syncthreads();
    }
    float* outs[3] = {g_xr, g_xz, g_xh};
#pragma unroll
    for (int w = 0; w < 3; w++)
#pragma unroll
        for (int mt = 0; mt < 2; mt++)
#pragma unroll
            for (int nt = 0; nt < 2; nt++) {
                int r = m0 + wm + mt * 16 + g;
                int c = n0 + wn + nt * 8 + 2 * tg;
                outs[w][(long)r * H_ + c]           = acc[w][mt][nt][0];
                outs[w][(long)r * H_ + c + 1]       = acc[w][mt][nt][1];
                outs[w][(long)(r + 8) * H_ + c]     = acc[w][mt][nt][2];
                outs[w][(long)(r + 8) * H_ + c + 1] = acc[w][mt][nt][3];
            }
}

// ---------------- hs partials (3xTF32): adj[rows,:] @ h, split-K=4 ----------
// chunk z: k in [z*1024, z*1024+1024). Partials -> g_rhs + z*CHUNK.
__global__ __launch_bounds__(256) void mm_hs_tc(const float* __restrict__ adj, int lvl) {
    int o0 = g_off[lvl];
    int M = g_off[lvl + 1] - o0;
    int m0 = blockIdx.y * 64;
    if (m0 >= M) return;
    const int* rows = g_rows + o0;
    int n0 = blockIdx.x * 64;
    int kbase = blockIdx.z * 1024;
    __shared__ float sAh[2][64][SP], sAl[2][64][SP], sBh[2][64][SP], sBl[2][64][SP];
    int wid = threadIdx.x >> 5, lane = threadIdx.x & 31;
    int g = lane >> 2, tg = lane & 3;
    int wm = (wid & 1) * 32, wn = (wid >> 1) * 16;
    float acc[2][2][4] = {};
    const int nsl = 1024 / BK;   // 64
    float4 ra = ldrawG(adj, N_, kbase, m0, M, rows);
    float4 rb = ldrawNN(g_h, kbase, n0);
    split_store(sAh[0], sAl[0], ra);
    split_storeNN(sBh[0], sBl[0], rb);
    __syncthreads();
    int cur = 0;
    for (int s = 0; s < nsl; s++) {
        if (s + 1 < nsl) {
            int k0 = kbase + (s + 1) * BK;
            ra = ldrawG(adj, N_, k0, m0, M, rows);
            rb = ldrawNN(g_h, k0, n0);
        }
        mma_tile(acc, sAh[cur], sAl[cur], sBh[cur], sBl[cur], wm, wn, g, tg);
        if (s + 1 < nsl) {
            split_store(sAh[1 - cur], sAl[1 - cur], ra);
            split_storeNN(sBh[1 - cur], sBl[1 - cur], rb);
        }
        __syncthreads();
        cur ^= 1;
    }
    float* P = g_rhs + (long)blockIdx.z * CHUNK;
#pragma unroll
    for (int mt = 0; mt < 2; mt++)
#pragma unroll
        for (int nt = 0; nt < 2; nt++) {
            int m = m0 + wm + mt * 16 + g;
            int c = n0 + wn + nt * 8 + 2 * tg;
            if (m < M) {
                P[(long)m * H_ + c]     = acc[mt][nt][0];
                P[(long)m * H_ + c + 1] = acc[mt][nt][1];
            }
            if (m + 8 < M) {
                P[(long)(m + 8) * H_ + c]     = acc[mt][nt][2];
                P[(long)(m + 8) * H_ + c + 1] = acc[mt][nt][3];
            }
        }
}
__global__ void reduce_hs_k(int lvl) {
    int M = g_off[lvl + 1] - g_off[lvl];
    long idx = (long)blockIdx.x * 256 + threadIdx.x;
    int m = (int)(idx >> 9);
    if (m >= M) return;
    g_hs[idx] = g_rhs[idx] + g_rhs[idx + CHUNK] +
                g_rhs[idx + 2L * CHUNK] + g_rhs[idx + 3L * CHUNK];
}

// ================= fp32 64x64x16 machinery (256 thr, 4x4/thread) =============
template <bool GATHER>
__device__ __forceinline__ float4 ldT(const float* __restrict__ src, long ld,
                                      int Klim, int k0, int r0, int M,
                                      const int* __restrict__ rows) {
    int lr = threadIdx.x >> 2;
    int lc = (threadIdx.x & 3) << 2;
    int gk = k0 + lc;
    int gm = r0 + lr;
    float4 v = make_float4(0.f, 0.f, 0.f, 0.f);
    if ((!GATHER || gm < M) && gk < Klim) {
        long r = GATHER ? (long)rows[gm] : (long)gm;
        v = *(const float4*)(src + r * ld + gk);
    }
    return v;
}
__device__ __forceinline__ void stT(float (*sD)[ST], float4 v) {
    int lr = threadIdx.x >> 2;
    int lc = (threadIdx.x & 3) << 2;
    sD[lc + 0][lr] = v.x; sD[lc + 1][lr] = v.y;
    sD[lc + 2][lr] = v.z; sD[lc + 3][lr] = v.w;
}
__device__ __forceinline__ void sl44(float ac[4][4], const float (*sA)[ST],
                                     const float (*sB)[ST], int ty, int tx) {
#pragma unroll
    for (int k = 0; k < BK; k++) {
        float a[4], b[4];
        *(float4*)a = *(const float4*)&sA[k][ty * 4];
        *(float4*)b = *(const float4*)&sB[k][tx * 4];
#pragma unroll
        for (int i = 0; i < 4; i++)
#pragma unroll
            for (int j = 0; j < 4; j++) ac[i][j] = fmaf(a[i], b[j], ac[i][j]);
    }
}
__device__ __forceinline__ void sl44d(float aR[4][4], float aZ[4][4],
                                      const float (*sA)[ST], const float (*sB1)[ST],
                                      const float (*sB2)[ST], int ty, int tx) {
#pragma unroll
    for (int k = 0; k < BK; k++) {
        float a[4], b1[4], b2[4];
        *(float4*)a  = *(const float4*)&sA[k][ty * 4];
        *(float4*)b1 = *(const float4*)&sB1[k][tx * 4];
        *(float4*)b2 = *(const float4*)&sB2[k][tx * 4];
#pragma unroll
        for (int i = 0; i < 4; i++)
#pragma unroll
            for (int j = 0; j < 4; j++) {
                aR[i][j] = fmaf(a[i], b1[j], aR[i][j]);
                aZ[i][j] = fmaf(a[i], b2[j], aZ[i][j]);
            }
    }
}

// ---------------- r & z gates: fp32, single phase K=512 ---------------------
__global__ __launch_bounds__(256) void mm_rz(const float* __restrict__ Ur,
                                             const float* __restrict__ Uz, int lvl) {
    int o0 = g_off[lvl];
    int M = g_off[lvl + 1] - o0;
    int m0 = blockIdx.y * 64;
    if (m0 >= M) return;
    const int* rows = g_rows + o0;
    int n0 = blockIdx.x * 64;
    __shared__ float sA[2][BK][ST], sB1[2][BK][ST], sB2[2][BK][ST];
    int ty = threadIdx.x >> 4, tx = threadIdx.x & 15;
    float aR[4][4] = {}, aZ[4][4] = {};
    const int nsl = H_ / BK;
    float4 ra = ldT<false>(g_hs, H_, H_, 0, m0, N_, nullptr);
    float4 r1 = ldT<false>(Ur, H_, H_, 0, n0, H_, nullptr);
    float4 r2 = ldT<false>(Uz, H_, H_, 0, n0, H_, nullptr);
    stT(sA[0], ra); stT(sB1[0], r1); stT(sB2[0], r2);
    __syncthreads();
    int cur = 0;
    for (int sl = 0; sl < nsl; sl++) {
        if (sl + 1 < nsl) {
            int k0 = (sl + 1) * BK;
            ra = ldT<false>(g_hs, H_, H_, k0, m0, N_, nullptr);
            r1 = ldT<false>(Ur, H_, H_, k0, n0, H_, nullptr);
            r2 = ldT<false>(Uz, H_, H_, k0, n0, H_, nullptr);
        }
        sl44d(aR, aZ, sA[cur], sB1[cur], sB2[cur], ty, tx);
        if (sl + 1 < nsl) { stT(sA[1 - cur], ra); stT(sB1[1 - cur], r1); stT(sB2[1 - cur], r2); }
        __syncthreads();
        cur ^= 1;
    }
#pragma unroll
    for (int i = 0; i < 4; i++) {
        int m = m0 + ty * 4 + i;
        if (m >= M) continue;
        long gr = rows[m];
#pragma unroll
        for (int j = 0; j < 4; j++) {
            int n = n0 + tx * 4 + j;
            long ci = (long)m * H_ + n;
            long gi = gr * H_ + n;
            float r = sigm_(g_xr[gi] + aR[i][j]);
            float z = sigm_(g_xz[gi] + aZ[i][j]);
            g_rhs[ci] = g_hs[ci] * r;
            g_h[gi] = z;   // stash
        }
    }
}

// ---------------- h-tilde + GRU combine: fp32, single phase K=512 -----------
__global__ __launch_bounds__(256) void mm_h(const float* __restrict__ Uh, int lvl) {
    int o0 = g_off[lvl];
    int M = g_off[lvl + 1] - o0;
    int m0 = blockIdx.y * 64;
    if (m0 >= M) return;
    const int* rows = g_rows + o0;
    int n0 = blockIdx.x * 64;
    __shared__ float sA[2][BK][ST], sB[2][BK][ST];
    int ty = threadIdx.x >> 4, tx = threadIdx.x & 15;
    float ac[4][4] = {};
    const int nsl = H_ / BK;
    float4 ra = ldT<false>(g_rhs, H_, H_, 0, m0, N_, nullptr);
    float4 rb = ldT<false>(Uh, H_, H_, 0, n0, H_, nullptr);
    stT(sA[0], ra); stT(sB[0], rb);
    __syncthreads();
    int cur = 0;
    for (int sl = 0; sl < nsl; sl++) {
        if (sl + 1 < nsl) {
            int k0 = (sl + 1) * BK;
            ra = ldT<false>(g_rhs, H_, H_, k0, m0, N_, nullptr);
            rb = ldT<false>(Uh, H_, H_, k0, n0, H_, nullptr);
        }
        sl44(ac, sA[cur], sB[cur], ty, tx);
        if (sl + 1 < nsl) { stT(sA[1 - cur], ra); stT(sB[1 - cur], rb); }
        __syncthreads();
        cur ^= 1;
    }
#pragma unroll
    for (int i = 0; i < 4; i++) {
        int m = m0 + ty * 4 + i;
        if (m >= M) continue;
        long gr = rows[m];
#pragma unroll
        for (int j = 0; j < 4; j++) {
            int n = n0 + tx * 4 + j;
            long ci = (long)m * H_ + n;
            long gi = gr * H_ + n;
            float hh = tanhf(g_xh[gi] + ac[i][j]);
            float z = g_h[gi];               // stashed by mm_rz
            float hs = g_hs[ci];
            g_h[gi] = (1.f - z) * hs + z * hh;
        }
    }
}

// ---------------- decoder ----------------
__global__ void decoder_k(const float* __restrict__ dw,
                          const float* __restrict__ db,
                          float* __restrict__ out) {
    int row = blockIdx.x;
    int tid = threadIdx.x;    // 128
    const float* hr = g_h + (long)row * H_;
    float a0 = 0.f, a1 = 0.f, a2 = 0.f, a3 = 0.f;
    for (int k = tid; k < H_; k += 128) {
        float hv = hr[k];
        a0 = fmaf(hv, dw[0 * H_ + k], a0);
        a1 = fmaf(hv, dw[1 * H_ + k], a1);
        a2 = fmaf(hv, dw[2 * H_ + k], a2);
        a3 = fmaf(hv, dw[3 * H_ + k], a3);
    }
#pragma unroll
    for (int o = 16; o > 0; o >>= 1) {
        a0 += __shfl_down_sync(0xFFFFFFFFu, a0, o);
        a1 += __shfl_down_sync(0xFFFFFFFFu, a1, o);
        a2 += __shfl_down_sync(0xFFFFFFFFu, a2, o);
        a3 += __shfl_down_sync(0xFFFFFFFFu, a3, o);
    }
    __shared__ float s[4][4];
    int w = tid >> 5, l = tid & 31;
    if (l == 0) { s[w][0] = a0; s[w][1] = a1; s[w][2] = a2; s[w][3] = a3; }
    __syncthreads();
    if (tid < C_)
        out[(long)row * C_ + tid] = s[0][tid] + s[1][tid] + s[2][tid] + s[3][tid] + db[tid];
}

// ---------------- static-init preload ----------------
namespace {
struct Preload {
    Preload() {
        cudaSetDevice(0);
        void* p = nullptr;
        cudaGetSymbolAddress(&p, g_h);
        cudaFuncAttributes at;
        cudaFuncGetAttributes(&at, mm_xhat);
        cudaFuncGetAttributes(&at, mm_xw);
        cudaFuncGetAttributes(&at, mm_hs_tc);
        cudaFuncGetAttributes(&at, reduce_hs_k);
        cudaFuncGetAttributes(&at, zero_hs_k);
        cudaFuncGetAttributes(&at, mm_rz);
        cudaFuncGetAttributes(&at, mm_h);
        cudaFuncGetAttributes(&at, decoder_k);
        lvl_init_k<<<1, 32>>>();
        lvl_scan_k<<<1, 32>>>();
        zero_h_k<<<256, 256>>>();
        cudaDeviceSynchronize();
        cudaGetLastError();
    }
};
Preload preload_;
}

// ---------------- launch ----------------
extern "C" void kernel_launch(void* const* d_in, const int* in_sizes, int n_in,
                              void* d_out, int out_size) {
    const float* x     = (const float*)d_in[0];
    const float* adj   = (const float*)d_in[1];
    const int*   level = (const int*)  d_in[2];
    const float* E_w   = (const float*)d_in[3];
    const float* Wr    = (const float*)d_in[4];
    const float* Wz    = (const float*)d_in[5];
    const float* Ur    = (const float*)d_in[6];
    const float* Uz    = (const float*)d_in[7];
    const float* Wh    = (const float*)d_in[8];
    const float* Uh    = (const float*)d_in[9];
    const float* dec_w = (const float*)d_in[10];
    const float* dec_b = (const float*)d_in[11];
    float* out = (float*)d_out;
    (void)in_sizes; (void)n_in; (void)out_size;

    lvl_init_k<<<1, 32>>>();
    lvl_hist_k<<<(N_ + 255) / 256, 256>>>(level);
    lvl_scan_k<<<1, 32>>>();
    lvl_scatter_k<<<(N_ + 255) / 256, 256>>>(level);
    zero_h_k<<<256, 256>>>();

    mm_xhat<<<dim3(H_ / 64, N_ / 64), 256>>>(x, E_w);
    mm_xw<<<dim3(H_ / 64, N_ / 64), 256>>>(Wr, Wz, Wh);

    const int RB = CHUNK / 256;
    for (int j = L_ - 1; j >= 0; j--) {
        if (j == L_ - 1) {
            // h == 0 at the deepest level -> hs == 0 exactly
            zero_hs_k<<<RB, 256>>>(j);
        } else {
            mm_hs_tc<<<dim3(8, 16, 4), 256>>>(adj, j);
            reduce_hs_k<<<RB, 256>>>(j);
        }
        mm_rz<<<dim3(8, 16), 256>>>(Ur, Uz, j);
        mm_h<<<dim3(8, 16), 256>>>(Uh, j);
    }

    decoder_k<<<N_, 128>>>(dec_w, dec_b, out);
}

// round 9
// speedup vs baseline: 1.2701x; 1.2701x over previous
#include <cuda_runtime.h>
#include <cstdint>

#define N_ 4096
#define D_ 5000
#define H_ 512
#define C_ 4
#define L_ 8
#define BK 16
#define ST 68
#define SAT 36
#define SP 20
#define CHUNK (1024 * 512)

// ---------------- scratch: 56 MiB ----------------
__device__ float g_xhat[N_ * H_];   // E(x), original row order
__device__ float g_xr[N_ * H_];     // compact order
__device__ float g_xz[N_ * H_];     // compact order
__device__ float g_xh[N_ * H_];     // compact order
__device__ float g_hc[N_ * H_];     // hidden state, COMPACT (level-sorted) order
__device__ float g_hs[N_ * H_];     // per-level hs (local rows 0..M)
__device__ float g_rhs[N_ * H_];    // chunks: split-K partials; then rhs(c0)+zstash(c1)
__device__ int   g_rows[N_];        // compact -> original, sorted within level
__device__ int   g_off[16];

// ---------------- level bucketing (deterministic, sorted) ----------------
__global__ void lvl_init_k() {
    int t = threadIdx.x;
    if (t < 16) g_off[t] = 0;
}
__global__ void lvl_hist_k(const int* __restrict__ level) {
    int i = blockIdx.x * blockDim.x + threadIdx.x;
    if (i < N_) atomicAdd(&g_off[level[i] + 1], 1);
}
__global__ void lvl_scan_k() {
    if (threadIdx.x == 0)
        for (int j = 1; j <= L_; j++) g_off[j] += g_off[j - 1];
}
// rank-based scatter: g_rows sorted ascending within each level bucket
__global__ void lvl_rank_k(const int* __restrict__ level) {
    __shared__ int slv[N_];
    for (int i = threadIdx.x; i < N_; i += blockDim.x) slv[i] = level[i];
    __syncthreads();
    int i = blockIdx.x * blockDim.x + threadIdx.x;
    if (i < N_) {
        int l = slv[i];
        int r = 0;
        for (int j = 0; j < i; j++) r += (slv[j] == l) ? 1 : 0;
        g_rows[g_off[l] + r] = i;
    }
}
// zero g_hs rows 0..M-1 (deepest level: h == 0 exactly)
__global__ void zero_hs_k(int lvl) {
    int M = g_off[lvl + 1] - g_off[lvl];
    long idx = (long)blockIdx.x * 256 + threadIdx.x;
    int m = (int)(idx >> 9);
    if (m < M) g_hs[idx] = 0.f;
}

__device__ __forceinline__ float sigm_(float v) { return 1.f / (1.f + expf(-v)); }

// ================= 3xTF32 mma machinery (validated) =================
__device__ __forceinline__ uint32_t fu(float f) { return __float_as_uint(f); }
__device__ __forceinline__ void tf32split(float v, float& hi, float& lo) {
    uint32_t b;
    asm("cvt.rna.tf32.f32 %0, %1;" : "=r"(b) : "f"(v));
    hi = __uint_as_float(b);
    lo = v - hi;
}
__device__ __forceinline__ void mma8(float c[4], const uint32_t a[4],
                                     uint32_t b0, uint32_t b1) {
    asm volatile(
        "mma.sync.aligned.m16n8k8.row.col.f32.tf32.tf32.f32 "
        "{%0,%1,%2,%3}, {%4,%5,%6,%7}, {%8,%9}, {%0,%1,%2,%3};"
        : "+f"(c[0]), "+f"(c[1]), "+f"(c[2]), "+f"(c[3])
        : "r"(a[0]), "r"(a[1]), "r"(a[2]), "r"(a[3]), "r"(b0), "r"(b1));
}
__device__ __forceinline__ float4 ldraw(const float* __restrict__ src, long ld,
                                        int K, int k0, int r0) {
    int lr = threadIdx.x >> 2;
    int lc = (threadIdx.x & 3) << 2;
    int gk = k0 + lc;
    float4 v = make_float4(0.f, 0.f, 0.f, 0.f);
    if (gk < K) v = *(const float4*)(src + (long)(r0 + lr) * ld + gk);
    return v;
}
__device__ __forceinline__ float4 ldrawG(const float* __restrict__ src, long ld,
                                         int k0, int r0,
                                         const int* __restrict__ rows) {
    int lr = threadIdx.x >> 2;
    int lc = (threadIdx.x & 3) << 2;
    return *(const float4*)(src + (long)rows[r0 + lr] * ld + k0 + lc);
}
__device__ __forceinline__ void split_store(float (*sH)[SP], float (*sL)[SP], float4 v) {
    int lr = threadIdx.x >> 2;
    int lc = (threadIdx.x & 3) << 2;
    float h0, l0, h1, l1, h2, l2, h3, l3;
    tf32split(v.x, h0, l0); tf32split(v.y, h1, l1);
    tf32split(v.z, h2, l2); tf32split(v.w, h3, l3);
    *(float4*)&sH[lr][lc] = make_float4(h0, h1, h2, h3);
    *(float4*)&sL[lr][lc] = make_float4(l0, l1, l2, l3);
}
__device__ __forceinline__ void mma_tile(float acc[2][2][4],
                                         const float (*sAh)[SP], const float (*sAl)[SP],
                                         const float (*sBh)[SP], const float (*sBl)[SP],
                                         int wm, int wn, int g, int tg) {
#pragma unroll
    for (int kk = 0; kk < 16; kk += 8) {
        uint32_t ah[2][4], al[2][4];
#pragma unroll
        for (int mt = 0; mt < 2; mt++) {
            int r0 = wm + mt * 16 + g;
            ah[mt][0] = fu(sAh[r0][kk + tg]);     ah[mt][1] = fu(sAh[r0 + 8][kk + tg]);
            ah[mt][2] = fu(sAh[r0][kk + tg + 4]); ah[mt][3] = fu(sAh[r0 + 8][kk + tg + 4]);
            al[mt][0] = fu(sAl[r0][kk + tg]);     al[mt][1] = fu(sAl[r0 + 8][kk + tg]);
            al[mt][2] = fu(sAl[r0][kk + tg + 4]); al[mt][3] = fu(sAl[r0 + 8][kk + tg + 4]);
        }
#pragma unroll
        for (int nt = 0; nt < 2; nt++) {
            int c = wn + nt * 8 + g;
            uint32_t bh0 = fu(sBh[c][kk + tg]), bh1 = fu(sBh[c][kk + tg + 4]);
            uint32_t bl0 = fu(sBl[c][kk + tg]), bl1 = fu(sBl[c][kk + tg + 4]);
#pragma unroll
            for (int mt = 0; mt < 2; mt++) {
                mma8(acc[mt][nt], ah[mt], bh0, bh1);
                mma8(acc[mt][nt], al[mt], bh0, bh1);
                mma8(acc[mt][nt], ah[mt], bl0, bl1);
            }
        }
    }
}

// ---------------- x_hat = x @ E_w^T  (3xTF32, double-buffered) ----------------
__global__ __launch_bounds__(256) void mm_xhat(const float* __restrict__ x,
                                               const float* __restrict__ Ew) {
    __shared__ float sAh[2][64][SP], sAl[2][64][SP], sBh[2][64][SP], sBl[2][64][SP];
    int m0 = blockIdx.y * 64, n0 = blockIdx.x * 64;
    int wid = threadIdx.x >> 5, lane = threadIdx.x & 31;
    int g = lane >> 2, tg = lane & 3;
    int wm = (wid & 1) * 32, wn = (wid >> 1) * 16;
    float acc[2][2][4] = {};
    const int nsl = (D_ + BK - 1) / BK;
    float4 ra = ldraw(x, D_, D_, 0, m0);
    float4 rb = ldraw(Ew, D_, D_, 0, n0);
    split_store(sAh[0], sAl[0], ra);
    split_store(sBh[0], sBl[0], rb);
    __syncthreads();
    int cur = 0;
    for (int s = 0; s < nsl; s++) {
        if (s + 1 < nsl) {
            ra = ldraw(x, D_, D_, (s + 1) * BK, m0);
            rb = ldraw(Ew, D_, D_, (s + 1) * BK, n0);
        }
        mma_tile(acc, sAh[cur], sAl[cur], sBh[cur], sBl[cur], wm, wn, g, tg);
        if (s + 1 < nsl) {
            split_store(sAh[1 - cur], sAl[1 - cur], ra);
            split_store(sBh[1 - cur], sBl[1 - cur], rb);
        }
        __syncthreads();
        cur ^= 1;
    }
#pragma unroll
    for (int mt = 0; mt < 2; mt++)
#pragma unroll
        for (int nt = 0; nt < 2; nt++) {
            int r = m0 + wm + mt * 16 + g;
            int c = n0 + wn + nt * 8 + 2 * tg;
            g_xhat[(long)r * H_ + c]           = acc[mt][nt][0];
            g_xhat[(long)r * H_ + c + 1]       = acc[mt][nt][1];
            g_xhat[(long)(r + 8) * H_ + c]     = acc[mt][nt][2];
            g_xhat[(long)(r + 8) * H_ + c + 1] = acc[mt][nt][3];
        }
}

// ------ xr/xz/xh[compact] = xhat[rows] @ {Wr,Wz,Wh}^T  (3xTF32, shared A) -----
__global__ __launch_bounds__(256) void mm_xw(const float* __restrict__ Wr,
                                             const float* __restrict__ Wz,
                                             const float* __restrict__ Wh) {
    __shared__ float sAh[64][SP], sAl[64][SP];
    __shared__ float sBh[3][64][SP], sBl[3][64][SP];
    int m0 = blockIdx.y * 64, n0 = blockIdx.x * 64;
    int wid = threadIdx.x >> 5, lane = threadIdx.x & 31;
    int g = lane >> 2, tg = lane & 3;
    int wm = (wid & 1) * 32, wn = (wid >> 1) * 16;
    float acc[3][2][2][4] = {};
    for (int k0 = 0; k0 < H_; k0 += BK) {
        split_store(sAh, sAl, ldrawG(g_xhat, H_, k0, m0, g_rows));
        split_store(sBh[0], sBl[0], ldraw(Wr, H_, H_, k0, n0));
        split_store(sBh[1], sBl[1], ldraw(Wz, H_, H_, k0, n0));
        split_store(sBh[2], sBl[2], ldraw(Wh, H_, H_, k0, n0));
        __syncthreads();
#pragma unroll
        for (int w = 0; w < 3; w++)
            mma_tile(acc[w], sAh, sAl, sBh[w], sBl[w], wm, wn, g, tg);
        __syncthreads();
    }
    float* outs[3] = {g_xr, g_xz, g_xh};
#pragma unroll
    for (int w = 0; w < 3; w++)
#pragma unroll
        for (int mt = 0; mt < 2; mt++)
#pragma unroll
            for (int nt = 0; nt < 2; nt++) {
                int r = m0 + wm + mt * 16 + g;       // compact row
                int c = n0 + wn + nt * 8 + 2 * tg;
                outs[w][(long)r * H_ + c]           = acc[w][mt][nt][0];
                outs[w][(long)r * H_ + c + 1]       = acc[w][mt][nt][1];
                outs[w][(long)(r + 8) * H_ + c]     = acc[w][mt][nt][2];
                outs[w][(long)(r + 8) * H_ + c + 1] = acc[w][mt][nt][3];
            }
}

// ================= fp32 tile slabs =================
__device__ __forceinline__ void sl44(float ac[4][4], const float (*sA)[ST],
                                     const float (*sB)[ST], int ty, int tx) {
#pragma unroll
    for (int k = 0; k < BK; k++) {
        float a[4], b[4];
        *(float4*)a = *(const float4*)&sA[k][ty * 4];
        *(float4*)b = *(const float4*)&sB[k][tx * 4];
#pragma unroll
        for (int i = 0; i < 4; i++)
#pragma unroll
            for (int j = 0; j < 4; j++) ac[i][j] = fmaf(a[i], b[j], ac[i][j]);
    }
}
__device__ __forceinline__ void sl24d(float aR[2][4], float aZ[2][4],
                                      const float (*sA)[SAT], const float (*sB1)[ST],
                                      const float (*sB2)[ST], int ty, int tx) {
#pragma unroll
    for (int k = 0; k < BK; k++) {
        float2 a = *(const float2*)&sA[k][ty * 2];
        float b1[4], b2[4];
        *(float4*)b1 = *(const float4*)&sB1[k][tx * 4];
        *(float4*)b2 = *(const float4*)&sB2[k][tx * 4];
#pragma unroll
        for (int j = 0; j < 4; j++) {
            aR[0][j] = fmaf(a.x, b1[j], aR[0][j]);
            aR[1][j] = fmaf(a.y, b1[j], aR[1][j]);
            aZ[0][j] = fmaf(a.x, b2[j], aZ[0][j]);
            aZ[1][j] = fmaf(a.y, b2[j], aZ[1][j]);
        }
    }
}
__device__ __forceinline__ void sl24(float ac[2][4], const float (*sA)[SAT],
                                     const float (*sB)[ST], int ty, int tx) {
#pragma unroll
    for (int k = 0; k < BK; k++) {
        float2 a = *(const float2*)&sA[k][ty * 2];
        float b[4];
        *(float4*)b = *(const float4*)&sB[k][tx * 4];
#pragma unroll
        for (int j = 0; j < 4; j++) {
            ac[0][j] = fmaf(a.x, b[j], ac[0][j]);
            ac[1][j] = fmaf(a.y, b[j], ac[1][j]);
        }
    }
}

// ---- hs partials (fp32, EXACT column-skip): adj[rows_j, cols_act] @ hc ------
// K runs only over already-computed compact rows [off[lvl+1], N). split-K=4.
__global__ __launch_bounds__(256) void mm_hs(const float* __restrict__ adj, int lvl) {
    int o0 = g_off[lvl], o1 = g_off[lvl + 1];
    int M = o1 - o0;
    int Ktot = N_ - o1;
    int m0 = blockIdx.y * 64;
    if (m0 >= M) return;
    const int* rows = g_rows + o0;
    const int* cols = g_rows + o1;
    int n0 = blockIdx.x * 64;
    int kchunk = ((Ktot + 63) >> 6) << 4;          // mult of 16, 4*kchunk >= Ktot
    int kbase = blockIdx.z * kchunk;
    int kend = min(kbase + kchunk, Ktot);
    int nsl = (kend > kbase) ? ((kend - kbase + 15) >> 4) : 0;

    int ty = threadIdx.x >> 4, tx = threadIdx.x & 15;
    float ac[4][4] = {};
    if (nsl > 0) {
        __shared__ float sA[2][BK][ST], sB[2][BK][ST];
        int alr = threadIdx.x >> 2;
        int alc = (threadIdx.x & 3) << 2;
        int gm = m0 + alr;
        long arow = (gm < M) ? (long)rows[gm] * N_ : -1;
        int bkk = threadIdx.x >> 4;
        int bc  = (threadIdx.x & 15) << 2;
        float va[4]; float4 vb;
        {
#pragma unroll
            for (int t = 0; t < 4; t++) {
                int k = kbase + alc + t;
                va[t] = (arow >= 0 && k < kend) ? adj[arow + cols[k]] : 0.f;
            }
            int kb = kbase + bkk;
            vb = (kb < kend) ? *(const float4*)(g_hc + (long)(o1 + kb) * H_ + n0 + bc)
                             : make_float4(0.f, 0.f, 0.f, 0.f);
        }
        sA[0][alc + 0][alr] = va[0]; sA[0][alc + 1][alr] = va[1];
        sA[0][alc + 2][alr] = va[2]; sA[0][alc + 3][alr] = va[3];
        *(float4*)&sB[0][bkk][bc] = vb;
        __syncthreads();
        int cur = 0;
        for (int sl = 0; sl < nsl; sl++) {
            if (sl + 1 < nsl) {
                int k0 = kbase + (sl + 1) * BK;
#pragma unroll
                for (int t = 0; t < 4; t++) {
                    int k = k0 + alc + t;
                    va[t] = (arow >= 0 && k < kend) ? adj[arow + cols[k]] : 0.f;
                }
                int kb = k0 + bkk;
                vb = (kb < kend) ? *(const float4*)(g_hc + (long)(o1 + kb) * H_ + n0 + bc)
                                 : make_float4(0.f, 0.f, 0.f, 0.f);
            }
            sl44(ac, sA[cur], sB[cur], ty, tx);
            if (sl + 1 < nsl) {
                sA[1 - cur][alc + 0][alr] = va[0]; sA[1 - cur][alc + 1][alr] = va[1];
                sA[1 - cur][alc + 2][alr] = va[2]; sA[1 - cur][alc + 3][alr] = va[3];
                *(float4*)&sB[1 - cur][bkk][bc] = vb;
            }
            __syncthreads();
            cur ^= 1;
        }
    }
    float* P = g_rhs + (long)blockIdx.z * CHUNK;
#pragma unroll
    for (int i = 0; i < 4; i++) {
        int m = m0 + ty * 4 + i;
        if (m >= M) continue;
        *(float4*)&P[(long)m * H_ + n0 + tx * 4] = *(float4*)&ac[i][0];
    }
}
__global__ void reduce_hs_k(int lvl) {
    int M = g_off[lvl + 1] - g_off[lvl];
    long idx = (long)blockIdx.x * 256 + threadIdx.x;
    int m = (int)(idx >> 9);
    if (m >= M) return;
    g_hs[idx] = g_rhs[idx] + g_rhs[idx + CHUNK] +
                g_rhs[idx + 2L * CHUNK] + g_rhs[idx + 3L * CHUNK];
}

// ---------------- r & z gates: fp32, BM=32, K=512 ---------------------------
__global__ __launch_bounds__(256) void mm_rz(const float* __restrict__ Ur,
                                             const float* __restrict__ Uz, int lvl) {
    int o0 = g_off[lvl];
    int M = g_off[lvl + 1] - o0;
    int m0 = blockIdx.y * 32;
    if (m0 >= M) return;
    int n0 = blockIdx.x * 64;
    __shared__ float sA[2][BK][SAT], sB1[2][BK][ST], sB2[2][BK][ST];
    int alr = threadIdx.x >> 3, alc = (threadIdx.x & 7) << 1;   // A: 32x16, float2
    int blr = threadIdx.x >> 2, blc = (threadIdx.x & 3) << 2;   // B: 64x16, float4
    int ty = threadIdx.x >> 4, tx = threadIdx.x & 15;
    float aR[2][4] = {}, aZ[2][4] = {};
    const int nsl = H_ / BK;
    float2 va; float4 v1, v2;
    va = *(const float2*)(g_hs + (long)(m0 + alr) * H_ + alc);
    v1 = *(const float4*)(Ur + (long)(n0 + blr) * H_ + blc);
    v2 = *(const float4*)(Uz + (long)(n0 + blr) * H_ + blc);
    sA[0][alc][alr] = va.x; sA[0][alc + 1][alr] = va.y;
    sB1[0][blc + 0][blr] = v1.x; sB1[0][blc + 1][blr] = v1.y;
    sB1[0][blc + 2][blr] = v1.z; sB1[0][blc + 3][blr] = v1.w;
    sB2[0][blc + 0][blr] = v2.x; sB2[0][blc + 1][blr] = v2.y;
    sB2[0][blc + 2][blr] = v2.z; sB2[0][blc + 3][blr] = v2.w;
    __syncthreads();
    int cur = 0;
    for (int sl = 0; sl < nsl; sl++) {
        if (sl + 1 < nsl) {
            int k0 = (sl + 1) * BK;
            va = *(const float2*)(g_hs + (long)(m0 + alr) * H_ + k0 + alc);
            v1 = *(const float4*)(Ur + (long)(n0 + blr) * H_ + k0 + blc);
            v2 = *(const float4*)(Uz + (long)(n0 + blr) * H_ + k0 + blc);
        }
        sl24d(aR, aZ, sA[cur], sB1[cur], sB2[cur], ty, tx);
        if (sl + 1 < nsl) {
            sA[1 - cur][alc][alr] = va.x; sA[1 - cur][alc + 1][alr] = va.y;
            sB1[1 - cur][blc + 0][blr] = v1.x; sB1[1 - cur][blc + 1][blr] = v1.y;
            sB1[1 - cur][blc + 2][blr] = v1.z; sB1[1 - cur][blc + 3][blr] = v1.w;
            sB2[1 - cur][blc + 0][blr] = v2.x; sB2[1 - cur][blc + 1][blr] = v2.y;
            sB2[1 - cur][blc + 2][blr] = v2.z; sB2[1 - cur][blc + 3][blr] = v2.w;
        }
        __syncthreads();
        cur ^= 1;
    }
#pragma unroll
    for (int i = 0; i < 2; i++) {
        int m = m0 + ty * 2 + i;
        if (m >= M) continue;
        long cr = (long)(o0 + m) * H_;     // compact global row
        long lm = (long)m * H_;            // level-local row
#pragma unroll
        for (int j = 0; j < 4; j++) {
            int n = n0 + tx * 4 + j;
            float av = (i == 0) ? aR[0][j] : aR[1][j];
            float zv = (i == 0) ? aZ[0][j] : aZ[1][j];
            float r = sigm_(g_xr[cr + n] + av);
            float z = sigm_(g_xz[cr + n] + zv);
            g_rhs[lm + n] = g_hs[lm + n] * r;
            g_rhs[CHUNK + lm + n] = z;     // z stash (chunk 1)
        }
    }
}

// ---------------- h-tilde + GRU combine: fp32, BM=32, K=512 -----------------
__global__ __launch_bounds__(256) void mm_h(const float* __restrict__ Uh, int lvl) {
    int o0 = g_off[lvl];
    int M = g_off[lvl + 1] - o0;
    int m0 = blockIdx.y * 32;
    if (m0 >= M) return;
    int n0 = blockIdx.x * 64;
    __shared__ float sA[2][BK][SAT], sB[2][BK][ST];
    int alr = threadIdx.x >> 3, alc = (threadIdx.x & 7) << 1;
    int blr = threadIdx.x >> 2, blc = (threadIdx.x & 3) << 2;
    int ty = threadIdx.x >> 4, tx = threadIdx.x & 15;
    float ac[2][4] = {};
    const int nsl = H_ / BK;
    float2 va; float4 vb;
    va = *(const float2*)(g_rhs + (long)(m0 + alr) * H_ + alc);
    vb = *(const float4*)(Uh + (long)(n0 + blr) * H_ + blc);
    sA[0][alc][alr] = va.x; sA[0][alc + 1][alr] = va.y;
    sB[0][blc + 0][blr] = vb.x; sB[0][blc + 1][blr] = vb.y;
    sB[0][blc + 2][blr] = vb.z; sB[0][blc + 3][blr] = vb.w;
    __syncthreads();
    int cur = 0;
    for (int sl = 0; sl < nsl; sl++) {
        if (sl + 1 < nsl) {
            int k0 = (sl + 1) * BK;
            va = *(const float2*)(g_rhs + (long)(m0 + alr) * H_ + k0 + alc);
            vb = *(const float4*)(Uh + (long)(n0 + blr) * H_ + k0 + blc);
        }
        sl24(ac, sA[cur], sB[cur], ty, tx);
        if (sl + 1 < nsl) {
            sA[1 - cur][alc][alr] = va.x; sA[1 - cur][alc + 1][alr] = va.y;
            sB[1 - cur][blc + 0][blr] = vb.x; sB[1 - cur][blc + 1][blr] = vb.y;
            sB[1 - cur][blc + 2][blr] = vb.z; sB[1 - cur][blc + 3][blr] = vb.w;
        }
        __syncthreads();
        cur ^= 1;
    }
#pragma unroll
    for (int i = 0; i < 2; i++) {
        int m = m0 + ty * 2 + i;
        if (m >= M) continue;
        long cr = (long)(o0 + m) * H_;
        long lm = (long)m * H_;
#pragma unroll
        for (int j = 0; j < 4; j++) {
            int n = n0 + tx * 4 + j;
            float av = (i == 0) ? ac[0][j] : ac[1][j];
            float hh = tanhf(g_xh[cr + n] + av);
            float z  = g_rhs[CHUNK + lm + n];
            float hs = g_hs[lm + n];
            g_hc[cr + n] = (1.f - z) * hs + z * hh;
        }
    }
}

// ---------------- decoder (compact -> original) ----------------
__global__ void decoder_k(const float* __restrict__ dw,
                          const float* __restrict__ db,
                          float* __restrict__ out) {
    int c = blockIdx.x;                      // compact row
    int tid = threadIdx.x;                   // 128
    const float* hr = g_hc + (long)c * H_;
    float a0 = 0.f, a1 = 0.f, a2 = 0.f, a3 = 0.f;
    for (int k = tid; k < H_; k += 128) {
        float hv = hr[k];
        a0 = fmaf(hv, dw[0 * H_ + k], a0);
        a1 = fmaf(hv, dw[1 * H_ + k], a1);
        a2 = fmaf(hv, dw[2 * H_ + k], a2);
        a3 = fmaf(hv, dw[3 * H_ + k], a3);
    }
#pragma unroll
    for (int o = 16; o > 0; o >>= 1) {
        a0 += __shfl_down_sync(0xFFFFFFFFu, a0, o);
        a1 += __shfl_down_sync(0xFFFFFFFFu, a1, o);
        a2 += __shfl_down_sync(0xFFFFFFFFu, a2, o);
        a3 += __shfl_down_sync(0xFFFFFFFFu, a3, o);
    }
    __shared__ float s[4][4];
    int w = tid >> 5, l = tid & 31;
    if (l == 0) { s[w][0] = a0; s[w][1] = a1; s[w][2] = a2; s[w][3] = a3; }
    __syncthreads();
    if (tid < C_) {
        int orig = g_rows[c];
        out[(long)orig * C_ + tid] = s[0][tid] + s[1][tid] + s[2][tid] + s[3][tid] + db[tid];
    }
}

// ---------------- static-init preload ----------------
namespace {
struct Preload {
    Preload() {
        cudaSetDevice(0);
        void* p = nullptr;
        cudaGetSymbolAddress(&p, g_hc);
        cudaFuncAttributes at;
        cudaFuncGetAttributes(&at, lvl_init_k);
        cudaFuncGetAttributes(&at, lvl_hist_k);
        cudaFuncGetAttributes(&at, lvl_scan_k);
        cudaFuncGetAttributes(&at, lvl_rank_k);
        cudaFuncGetAttributes(&at, zero_hs_k);
        cudaFuncGetAttributes(&at, mm_xhat);
        cudaFuncGetAttributes(&at, mm_xw);
        cudaFuncGetAttributes(&at, mm_hs);
        cudaFuncGetAttributes(&at, reduce_hs_k);
        cudaFuncGetAttributes(&at, mm_rz);
        cudaFuncGetAttributes(&at, mm_h);
        cudaFuncGetAttributes(&at, decoder_k);
        lvl_init_k<<<1, 32>>>();
        lvl_scan_k<<<1, 32>>>();
        cudaDeviceSynchronize();
        cudaGetLastError();
    }
};
Preload preload_;
}

// ---------------- launch ----------------
extern "C" void kernel_launch(void* const* d_in, const int* in_sizes, int n_in,
                              void* d_out, int out_size) {
    const float* x     = (const float*)d_in[0];
    const float* adj   = (const float*)d_in[1];
    const int*   level = (const int*)  d_in[2];
    const float* E_w   = (const float*)d_in[3];
    const float* Wr    = (const float*)d_in[4];
    const float* Wz    = (const float*)d_in[5];
    const float* Ur    = (const float*)d_in[6];
    const float* Uz    = (const float*)d_in[7];
    const float* Wh    = (const float*)d_in[8];
    const float* Uh    = (const float*)d_in[9];
    const float* dec_w = (const float*)d_in[10];
    const float* dec_b = (const float*)d_in[11];
    float* out = (float*)d_out;
    (void)in_sizes; (void)n_in; (void)out_size;

    lvl_init_k<<<1, 32>>>();
    lvl_hist_k<<<(N_ + 255) / 256, 256>>>(level);
    lvl_scan_k<<<1, 32>>>();
    lvl_rank_k<<<N_ / 256, 256>>>(level);

    mm_xhat<<<dim3(H_ / 64, N_ / 64), 256>>>(x, E_w);
    mm_xw<<<dim3(H_ / 64, N_ / 64), 256>>>(Wr, Wz, Wh);

    const int RB = CHUNK / 256;
    for (int j = L_ - 1; j >= 0; j--) {
        if (j == L_ - 1) {
            zero_hs_k<<<RB, 256>>>(j);           // K = 0: hs == 0 exactly
        } else {
            mm_hs<<<dim3(8, 16, 4), 256>>>(adj, j);
            reduce_hs_k<<<RB, 256>>>(j);
        }
        mm_rz<<<dim3(8, 32), 256>>>(Ur, Uz, j);
        mm_h<<<dim3(8, 32), 256>>>(Uh, j);
    }

    decoder_k<<<N_, 128>>>(dec_w, dec_b, out);
}